// round 14
// baseline (speedup 1.0000x reference)
#include <cuda_runtime.h>
#include <cuda_bf16.h>
#include <cuda_fp8.h>
#include <cstdint>

#define BATCH 8
#define EPSBN 1e-5f
#define ABLK  110592
#define WOFF2 36864
#define PW    258            // padded width (1-px halo each side)

// ---------------- scratch globals (all referenced ONLY in device code) ----------
__device__ float g_y1[(size_t)8 * 128 * 256 * 256];            // 256 MB
__device__ float g_sum1[128], g_sqs1[128], g_sum2[128], g_sqs2[128];
__device__ float g_a1[128], g_b1[128], g_a2[128], g_b2[128];

// padded activations [b][y+1][x+1][ci]: bf16 Ah, e4m3(Ah), e4m3(al*512)
__device__ __align__(16) __nv_bfloat16 g_x1hi[(size_t)8 * PW * PW * 64];
__device__ __align__(16) unsigned char g_x18h[(size_t)8 * PW * PW * 64];
__device__ __align__(16) unsigned char g_x18l[(size_t)8 * PW * PW * 64];
__device__ __align__(16) __nv_bfloat16 g_x2hi[(size_t)8 * PW * PW * 128];
__device__ __align__(16) unsigned char g_x28h[(size_t)8 * PW * PW * 128];
__device__ __align__(16) unsigned char g_x28l[(size_t)8 * PW * PW * 128];
// weight tiles, k-chunk 16: bf16 = [tile][64 oc][16ci] of Wh*512;
// fp8   = [tile][64 oc][32B]: bytes0-15 e4m3(wl*512), 16-31 e4m3(Wh)
__device__ __align__(16) __nv_bfloat16 g_wsh1hi[36 * 1024];
__device__ __align__(16) unsigned char g_wsh18[36 * 2048];
__device__ __align__(16) __nv_bfloat16 g_wsh2hi[72 * 1024];
__device__ __align__(16) unsigned char g_wsh28[72 * 2048];
__device__ __align__(16) __nv_bfloat16 g_wdy1hi[(size_t)512 * 36 * 1024];
__device__ __align__(16) unsigned char g_wdy18[(size_t)512 * 36 * 2048];
__device__ __align__(16) __nv_bfloat16 g_wdy2hi[(size_t)512 * 72 * 1024];
__device__ __align__(16) unsigned char g_wdy28[(size_t)512 * 72 * 2048];

// ---------------- helpers -------------------------------------------------------
__device__ __forceinline__ uint32_t smem_u32(const void* p) {
    uint32_t a;
    asm("{ .reg .u64 t; cvta.to.shared.u64 t, %1; cvt.u32.u64 %0, t; }"
        : "=r"(a) : "l"(p));
    return a;
}
#define LDM4(r, a) \
    asm volatile("ldmatrix.sync.aligned.m8n8.x4.shared.b16 {%0,%1,%2,%3}, [%4];" \
                 : "=r"((r)[0]), "=r"((r)[1]), "=r"((r)[2]), "=r"((r)[3]) : "r"(a))
#define MMA(d, a, b0, b1) \
    asm volatile("mma.sync.aligned.m16n8k16.row.col.f32.bf16.bf16.f32 " \
                 "{%0,%1,%2,%3},{%4,%5,%6,%7},{%8,%9},{%0,%1,%2,%3};" \
                 : "+f"((d)[0]), "+f"((d)[1]), "+f"((d)[2]), "+f"((d)[3]) \
                 : "r"((a)[0]), "r"((a)[1]), "r"((a)[2]), "r"((a)[3]), "r"(b0), "r"(b1))
#define MMA8(d, a, b0, b1) \
    asm volatile("mma.sync.aligned.m16n8k32.row.col.f32.e4m3.e4m3.f32 " \
                 "{%0,%1,%2,%3},{%4,%5,%6,%7},{%8,%9},{%0,%1,%2,%3};" \
                 : "+f"((d)[0]), "+f"((d)[1]), "+f"((d)[2]), "+f"((d)[3]) \
                 : "r"((a)[0]), "r"((a)[1]), "r"((a)[2]), "r"((a)[3]), "r"(b0), "r"(b1))

__device__ __forceinline__ uint32_t pkbf(float lo, float hi) {
    return (uint32_t)__bfloat16_as_ushort(__float2bfloat16(lo)) |
           ((uint32_t)__bfloat16_as_ushort(__float2bfloat16(hi)) << 16);
}
__device__ __forceinline__ unsigned char f2e4m3(float v) {
    return (unsigned char)__nv_cvt_float_to_fp8(v, __NV_SATFINITE, __NV_E4M3);
}
__device__ __forceinline__ uint32_t pk4e4m3(float a, float b, float c, float d) {
    return (uint32_t)f2e4m3(a) | ((uint32_t)f2e4m3(b) << 8) |
           ((uint32_t)f2e4m3(c) << 16) | ((uint32_t)f2e4m3(d) << 24);
}

// double-buffered static smem: per buffer A_BF/A_8/W_BF/W_8, 128 rows x 48B stride
static constexpr int S_A8  = 6144;
static constexpr int S_WBF = 12288;
static constexpr int S_W8  = 18432;
static constexpr int S_BUF = 24576;
static constexpr int SMEM_TOTAL = 49152;   // exactly 48KB static
static constexpr float INV_S = 1.f / 512.f;

// ---------------- small kernels -------------------------------------------------
__global__ void zero_stats_kernel() {
    int t = threadIdx.x;
    if (t < 128) { g_sum1[t] = 0.f; g_sqs1[t] = 0.f; g_sum2[t] = 0.f; g_sqs2[t] = 0.f; }
}

__global__ void zero_border_kernel() {
    int idx = blockIdx.x * 256 + threadIdx.x;
    if (idx >= 8 * 1028) return;
    int b = idx / 1028, s = idx % 1028;
    int y, x;
    if (s < 258)      { y = 0;           x = s; }
    else if (s < 516) { y = 257;         x = s - 258; }
    else if (s < 772) { y = s - 516 + 1; x = 0; }
    else              { y = s - 772 + 1; x = 257; }
    size_t p = ((size_t)b * PW + y) * PW + x;
    uint4 z = make_uint4(0, 0, 0, 0);
    uint4* h1 = (uint4*)(g_x1hi + p * 64);
    #pragma unroll
    for (int i = 0; i < 8; ++i) h1[i] = z;
    uint4* a1 = (uint4*)(g_x18h + p * 64);
    uint4* b1 = (uint4*)(g_x18l + p * 64);
    #pragma unroll
    for (int i = 0; i < 4; ++i) { a1[i] = z; b1[i] = z; }
    uint4* h2 = (uint4*)(g_x2hi + p * 128);
    #pragma unroll
    for (int i = 0; i < 16; ++i) h2[i] = z;
    uint4* a2 = (uint4*)(g_x28h + p * 128);
    uint4* b2 = (uint4*)(g_x28l + p * 128);
    #pragma unroll
    for (int i = 0; i < 8; ++i) { a2[i] = z; b2[i] = z; }
}

// x -> padded [b][y+1][x+1][ci]: bf16 Ah + e4m3(Ah) + e4m3(al*512)
template<int CIN, int LAYER>
__global__ void xsplit_kernel(const float* __restrict__ xin)
{
    __shared__ float tile[CIN][65];
    const int blk = blockIdx.x;
    const int xb = blk & 3, y = (blk >> 2) & 255, b = blk >> 10;
    const int tid = threadIdx.x;
    const float* src = (LAYER == 1) ? xin : (const float*)g_y1;
    __nv_bfloat16* dhi = (LAYER == 1) ? g_x1hi : g_x2hi;
    unsigned char* d8h = (LAYER == 1) ? g_x18h : g_x28h;
    unsigned char* d8l = (LAYER == 1) ? g_x18l : g_x28l;

    for (int i = tid; i < CIN * 64; i += 256) {
        int c = i >> 6, x = i & 63;
        float v = src[(((size_t)(b * CIN + c)) << 16) + (y << 8) + (xb << 6) + x];
        if (LAYER == 2) v = fmaxf(0.f, fmaf(g_a1[c], v, g_b1[c]));
        tile[c][x] = v;
    }
    __syncthreads();

    const int GSH = (CIN == 64) ? 3 : 4;
    const int GP  = CIN / 8;
    for (int i = tid; i < 64 * GP; i += 256) {
        int x = i >> GSH, g = i & (GP - 1);
        float v[8], hv[8];
        #pragma unroll
        for (int j = 0; j < 8; ++j) {
            v[j]  = tile[g * 8 + j][x];
            hv[j] = __bfloat162float(__float2bfloat16(v[j]));
        }
        uint4 uh;
        uh.x = pkbf(hv[0], hv[1]); uh.y = pkbf(hv[2], hv[3]);
        uh.z = pkbf(hv[4], hv[5]); uh.w = pkbf(hv[6], hv[7]);
        uint2 u8h, u8l;
        u8h.x = pk4e4m3(hv[0], hv[1], hv[2], hv[3]);
        u8h.y = pk4e4m3(hv[4], hv[5], hv[6], hv[7]);
        u8l.x = pk4e4m3((v[0] - hv[0]) * 512.f, (v[1] - hv[1]) * 512.f,
                        (v[2] - hv[2]) * 512.f, (v[3] - hv[3]) * 512.f);
        u8l.y = pk4e4m3((v[4] - hv[4]) * 512.f, (v[5] - hv[5]) * 512.f,
                        (v[6] - hv[6]) * 512.f, (v[7] - hv[7]) * 512.f);
        size_t off = (((size_t)b * PW + (y + 1)) * PW + (xb * 64 + x + 1)) * CIN + g * 8;
        *(uint4*)((char*)dhi + off * 2) = uh;
        *(uint2*)(d8h + off) = u8h;
        *(uint2*)(d8l + off) = u8l;
    }
}

// shared weights -> tiles: bf16 Wh*512 + fp8 [wl*512 | Wh]
template<int CIN, int LAYER>
__global__ void wprep_sh_kernel(const float* __restrict__ wsh)
{
    int idx = blockIdx.x * 256 + threadIdx.x;
    if (idx >= 64 * CIN) return;
    int ci = idx & (CIN - 1);
    int oc = idx >> ((CIN == 64) ? 6 : 7);
    constexpr int NS = CIN / 16;
    int sub = ci >> 4, cl = ci & 15;
    const float* s = wsh + ((size_t)oc * CIN + ci) * 9;
    __nv_bfloat16* hi = (LAYER == 1) ? g_wsh1hi : g_wsh2hi;
    unsigned char* w8 = (LAYER == 1) ? g_wsh18 : g_wsh28;
    #pragma unroll
    for (int k = 0; k < 9; ++k) {
        float v = s[k];
        float hv = __bfloat162float(__float2bfloat16(v));
        size_t t = (size_t)(k * NS + sub);
        hi[t * 1024 + oc * 16 + cl] = __float2bfloat16(hv * 512.f);
        w8[t * 2048 + oc * 32 + cl]      = f2e4m3((v - hv) * 512.f);
        w8[t * 2048 + oc * 32 + 16 + cl] = f2e4m3(hv);
    }
}

// dynamic weights -> tiles (same formats)
template<int CIN, int WOFF, int LAYER>
__global__ void wprep_dy_kernel(const float* __restrict__ cw)
{
    const long long idx = (long long)blockIdx.x * 256 + threadIdx.x;
    constexpr int LC = (CIN == 64) ? 6 : 7;
    const int ci = (int)(idx & (CIN - 1));
    const int oc = (int)((idx >> LC) & 63);
    const int bp = (int)(idx >> (LC + 6));
    constexpr int NS = CIN / 16;
    const int sub = ci >> 4, cl = ci & 15;
    const float* s = cw + (size_t)bp * ABLK + WOFF + ((size_t)oc * CIN + ci) * 9;
    __nv_bfloat16* hi = (LAYER == 1) ? g_wdy1hi : g_wdy2hi;
    unsigned char* w8 = (LAYER == 1) ? g_wdy18 : g_wdy28;
    #pragma unroll
    for (int k = 0; k < 9; ++k) {
        float v = s[k];
        float hv = __bfloat162float(__float2bfloat16(v));
        size_t t = (size_t)bp * (9 * NS) + k * NS + sub;
        hi[t * 1024 + oc * 16 + cl] = __float2bfloat16(hv * 512.f);
        w8[t * 2048 + oc * 32 + cl]      = f2e4m3((v - hv) * 512.f);
        w8[t * 2048 + oc * 32 + 16 + cl] = f2e4m3(hv);
    }
}

// ---------------- main conv: bf16 main + fp8 k-concat correction MMA -------------
// CTA = (b, patch, 4-row quad). D[128 px][128 oc]; 8 warps x (64px x 32oc).
// Per chunk: 16 bf16 m16n8k16 (Ah*Wh*512) + 16 e4m3 m16n8k32 (512*(Ah*wl+al*Wh)).
template<int CIN, int LAYER>
__global__ void __launch_bounds__(256, 2)
conv_mma_kernel(float* __restrict__ dout)
{
    __shared__ __align__(16) unsigned char sm[SMEM_TOTAL];
    const uint32_t sbase = smem_u32(sm);
    const int tid = threadIdx.x, lane = tid & 31, wid = tid >> 5;
    const int wm = wid & 1, wn = wid >> 1;

    const __nv_bfloat16* xhi = (LAYER == 1) ? g_x1hi : g_x2hi;
    const unsigned char* x8h = (LAYER == 1) ? g_x18h : g_x28h;
    const unsigned char* x8l = (LAYER == 1) ? g_x18l : g_x28l;
    const __nv_bfloat16* wshhi = (LAYER == 1) ? g_wsh1hi : g_wsh2hi;
    const unsigned char* wsh8  = (LAYER == 1) ? g_wsh18 : g_wsh28;
    const __nv_bfloat16* wdyhi = (LAYER == 1) ? g_wdy1hi : g_wdy2hi;
    const unsigned char* wdy8  = (LAYER == 1) ? g_wdy18 : g_wdy28;
    float* dst = (LAYER == 1) ? (float*)g_y1 : dout;

    const int blk = blockIdx.x;
    const int b = blk >> 9, p = (blk >> 3) & 63, q = blk & 7;
    const int y0 = ((p >> 3) << 5) + (q << 2);
    const int x0 = (p & 7) << 5;
    const int bp = b * 64 + p;
    constexpr int NS = CIN / 16;
    constexpr int NC = 9 * NS;

    float d[4][4][4];
    #pragma unroll
    for (int i = 0; i < 4; ++i)
        #pragma unroll
        for (int j = 0; j < 4; ++j)
            #pragma unroll
            for (int k = 0; k < 4; ++k) d[i][j][k] = 0.f;

    const uint32_t laneA = (uint32_t)(lane & 15) * 48 + (uint32_t)(lane >> 4) * 16;
    const uint32_t laneW = (uint32_t)((lane & 7) + ((lane >> 4) << 3)) * 48 +
                           (uint32_t)((lane >> 3) & 1) * 16;
    const int g8 = lane >> 2, t4 = lane & 3;   // fp8 fragment lane mapping

    const int px = tid >> 1, seg = tid & 1;
    const int wrow = tid >> 1;

    uint4 pfAb, pfA8, pfWb, pfW8;

    auto prefetch = [&](int cc) {
        const int tap = cc / NS, sub = cc - tap * NS;
        const int ky = tap / 3, kx = tap - ky * 3;
        const int y = y0 + (px >> 5) + ky;
        const int x = x0 + (px & 31) + kx;
        const size_t pbase = (((size_t)b * PW + y) * PW + x) * CIN + sub * 16;
        pfAb = *(const uint4*)(xhi + pbase + seg * 8);
        pfA8 = seg ? *(const uint4*)(x8l + pbase) : *(const uint4*)(x8h + pbase);
        if (wrow < 64) {
            pfWb = *(const uint4*)(wshhi + (size_t)cc * 1024 + wrow * 16 + seg * 8);
            pfW8 = *(const uint4*)(wsh8 + (size_t)cc * 2048 + wrow * 32 + seg * 16);
        } else {
            const size_t tb = (size_t)bp * NC + cc;
            pfWb = *(const uint4*)(wdyhi + tb * 1024 + (wrow - 64) * 16 + seg * 8);
            pfW8 = *(const uint4*)(wdy8 + tb * 2048 + (wrow - 64) * 32 + seg * 16);
        }
    };
    auto sts = [&](int buf) {
        unsigned char* bb = sm + buf * S_BUF;
        *(uint4*)(bb + px * 48 + seg * 16)           = pfAb;
        *(uint4*)(bb + S_A8 + px * 48 + seg * 16)    = pfA8;
        *(uint4*)(bb + S_WBF + wrow * 48 + seg * 16) = pfWb;
        *(uint4*)(bb + S_W8 + wrow * 48 + seg * 16)  = pfW8;
    };

    prefetch(0);
    sts(0);
    if (NC > 1) prefetch(1);
    __syncthreads();

    for (int cc = 0; cc < NC; ++cc) {
        const int buf = cc & 1;
        const uint32_t bufb = sbase + buf * S_BUF;
        // ---- bf16 main pass: Ah * (Wh*512) ----
        const uint32_t Ah = bufb + wm * 3072 + laneA;
        const uint32_t Wh = bufb + S_WBF + wn * 1536 + laneW;
        uint32_t a[4][4], w[2][4];
        #pragma unroll
        for (int mf = 0; mf < 4; ++mf) LDM4(a[mf], Ah + mf * 768);
        #pragma unroll
        for (int nf = 0; nf < 2; ++nf) LDM4(w[nf], Wh + nf * 768);
        #pragma unroll
        for (int mf = 0; mf < 4; ++mf)
            #pragma unroll
            for (int nf = 0; nf < 2; ++nf) {
                MMA(d[mf][nf * 2],     a[mf], w[nf][0], w[nf][1]);
                MMA(d[mf][nf * 2 + 1], a[mf], w[nf][2], w[nf][3]);
            }
        // ---- fp8 correction pass: [Ah|al*512] x [wl*512|Wh], K=32 ----
        const unsigned char* A8 = sm + buf * S_BUF + S_A8 + wm * 3072;
        const unsigned char* W8 = sm + buf * S_BUF + S_W8 + wn * 1536;
        uint32_t a8[4][4], b8[4][2];
        #pragma unroll
        for (int mf = 0; mf < 4; ++mf) {
            const unsigned char* ap = A8 + (mf * 16 + g8) * 48 + t4 * 4;
            a8[mf][0] = *(const uint32_t*)(ap);
            a8[mf][1] = *(const uint32_t*)(ap + 384);
            a8[mf][2] = *(const uint32_t*)(ap + 16);
            a8[mf][3] = *(const uint32_t*)(ap + 400);
        }
        #pragma unroll
        for (int n8 = 0; n8 < 4; ++n8) {
            const unsigned char* wp = W8 + (n8 * 8 + g8) * 48 + t4 * 4;
            b8[n8][0] = *(const uint32_t*)(wp);
            b8[n8][1] = *(const uint32_t*)(wp + 16);
        }
        #pragma unroll
        for (int mf = 0; mf < 4; ++mf)
            #pragma unroll
            for (int n8 = 0; n8 < 4; ++n8)
                MMA8(d[mf][n8], a8[mf], b8[n8][0], b8[n8][1]);
        // ---- fill other buffer for next chunk, start LDG for chunk+2 ----
        if (cc + 1 < NC) {
            sts(buf ^ 1);
            if (cc + 2 < NC) prefetch(cc + 2);
            __syncthreads();
        }
    }

    // ---- rescale (everything accumulated at x512) ----
    #pragma unroll
    for (int i = 0; i < 4; ++i)
        #pragma unroll
        for (int j = 0; j < 4; ++j)
            #pragma unroll
            for (int k = 0; k < 4; ++k) d[i][j][k] *= INV_S;

    // ---- epilogue: store + fused BN stats ----
    float* gsum = (LAYER == 1) ? g_sum1 : g_sum2;
    float* gsqs = (LAYER == 1) ? g_sqs1 : g_sqs2;
    const int r4 = lane >> 2;
    const int c2 = (lane & 3) << 1;
    #pragma unroll
    for (int mf = 0; mf < 4; ++mf) {
        int pxA = wm * 64 + mf * 16 + r4;
        int pxB = pxA + 8;
        size_t pixA = (size_t)(y0 + (pxA >> 5)) * 256 + x0 + (pxA & 31);
        size_t pixB = (size_t)(y0 + (pxB >> 5)) * 256 + x0 + (pxB & 31);
        #pragma unroll
        for (int n8 = 0; n8 < 4; ++n8) {
            int oc = wn * 32 + n8 * 8 + c2;
            size_t base = ((size_t)(b * 128 + oc)) << 16;
            dst[base + pixA]         = d[mf][n8][0];
            dst[base + 65536 + pixA] = d[mf][n8][1];
            dst[base + pixB]         = d[mf][n8][2];
            dst[base + 65536 + pixB] = d[mf][n8][3];
        }
    }
    #pragma unroll
    for (int n8 = 0; n8 < 4; ++n8) {
        float sA = 0.f, qA = 0.f, sB = 0.f, qB = 0.f;
        #pragma unroll
        for (int mf = 0; mf < 4; ++mf) {
            float e0 = d[mf][n8][0], e1 = d[mf][n8][1];
            float e2 = d[mf][n8][2], e3 = d[mf][n8][3];
            sA += e0 + e2; qA = fmaf(e0, e0, fmaf(e2, e2, qA));
            sB += e1 + e3; qB = fmaf(e1, e1, fmaf(e3, e3, qB));
        }
        #pragma unroll
        for (int off = 16; off >= 4; off >>= 1) {
            sA += __shfl_down_sync(0xffffffffu, sA, off);
            qA += __shfl_down_sync(0xffffffffu, qA, off);
            sB += __shfl_down_sync(0xffffffffu, sB, off);
            qB += __shfl_down_sync(0xffffffffu, qB, off);
        }
        if (lane < 4) {
            int oc = wn * 32 + n8 * 8 + c2;
            atomicAdd(&gsum[oc], sA);     atomicAdd(&gsqs[oc], qA);
            atomicAdd(&gsum[oc + 1], sB); atomicAdd(&gsqs[oc + 1], qB);
        }
    }
}

// ---------------- BN finalize / apply -------------------------------------------
__global__ void finalize_stats_kernel(const float* __restrict__ gamma,
                                      const float* __restrict__ beta, int layer)
{
    int c = threadIdx.x;
    if (c >= 128) return;
    const float invN = 1.f / (float)((size_t)BATCH * 256 * 256);
    float s = (layer == 1) ? g_sum1[c] : g_sum2[c];
    float q = (layer == 1) ? g_sqs1[c] : g_sqs2[c];
    float m = s * invN;
    float var = fmaf(-m, m, q * invN);
    float inv = rsqrtf(var + EPSBN);
    float a = gamma[c] * inv;
    float bb = fmaf(-a, m, beta[c]);
    if (layer == 1) { g_a1[c] = a; g_b1[c] = bb; }
    else            { g_a2[c] = a; g_b2[c] = bb; }
}

__global__ void apply_bn2_kernel(float4* __restrict__ out)
{
    const size_t n4 = (size_t)BATCH * 128 * 256 * 256 / 4;
    for (size_t i = (size_t)blockIdx.x * blockDim.x + threadIdx.x; i < n4;
         i += (size_t)gridDim.x * blockDim.x) {
        int c = (int)((i >> 14) & 127);
        float a = g_a2[c], bb = g_b2[c];
        float4 v = out[i];
        v.x = fmaxf(0.f, fmaf(a, v.x, bb));
        v.y = fmaxf(0.f, fmaf(a, v.y, bb));
        v.z = fmaxf(0.f, fmaf(a, v.z, bb));
        v.w = fmaxf(0.f, fmaf(a, v.w, bb));
        out[i] = v;
    }
}

// ---------------- launcher (harness pointers ONLY as kernel args) ----------------
extern "C" void kernel_launch(void* const* d_in, const int* in_sizes, int n_in,
                              void* d_out, int out_size)
{
    const float* x      = (const float*)d_in[0];
    const float* cw     = (const float*)d_in[1];
    const float* w1     = (const float*)d_in[2];
    const float* w2     = (const float*)d_in[3];
    const float* gamma1 = (const float*)d_in[4];
    const float* beta1  = (const float*)d_in[5];
    const float* gamma2 = (const float*)d_in[6];
    const float* beta2  = (const float*)d_in[7];
    float* out = (float*)d_out;

    zero_stats_kernel<<<1, 128>>>();
    zero_border_kernel<<<33, 256>>>();
    wprep_sh_kernel<64, 1><<<16, 256>>>(w1);
    wprep_sh_kernel<128, 2><<<32, 256>>>(w2);
    wprep_dy_kernel<64, 0, 1><<<8192, 256>>>(cw);
    wprep_dy_kernel<128, WOFF2, 2><<<16384, 256>>>(cw);

    // layer 1
    xsplit_kernel<64, 1><<<8192, 256>>>(x);
    conv_mma_kernel<64, 1><<<4096, 256>>>(nullptr);
    finalize_stats_kernel<<<1, 128>>>(gamma1, beta1, 1);

    // layer 2 (BN1+ReLU fused into xsplit)
    xsplit_kernel<128, 2><<<8192, 256>>>(nullptr);
    conv_mma_kernel<128, 2><<<4096, 256>>>(out);
    finalize_stats_kernel<<<1, 128>>>(gamma2, beta2, 2);

    apply_bn2_kernel<<<8192, 256>>>((float4*)out);
}

// round 15
// speedup vs baseline: 1.1173x; 1.1173x over previous
#include <cuda_runtime.h>
#include <cuda_bf16.h>
#include <cstdint>

#define BATCH 8
#define EPSBN 1e-5f
#define ABLK  110592
#define WOFF2 36864
#define PW    258            // padded width (1-px halo each side)

// ---------------- scratch globals (all referenced ONLY in device code) ----------
__device__ float g_y1[(size_t)8 * 128 * 256 * 256];            // 256 MB
__device__ float g_sum1[128], g_sqs1[128], g_sum2[128], g_sqs2[128];
__device__ float g_a1[128], g_b1[128], g_a2[128], g_b2[128];

// padded split activations [b][y+1][x+1][ci] bf16
__device__ __align__(16) __nv_bfloat16 g_x1hi[(size_t)8 * PW * PW * 64];
__device__ __align__(16) __nv_bfloat16 g_x1lo[(size_t)8 * PW * PW * 64];
__device__ __align__(16) __nv_bfloat16 g_x2hi[(size_t)8 * PW * PW * 128];
__device__ __align__(16) __nv_bfloat16 g_x2lo[(size_t)8 * PW * PW * 128];
// weight tiles, k-chunk 16: [(k*NS)+sub][64 oc][16 ci]
__device__ __align__(16) __nv_bfloat16 g_wsh1hi[36 * 1024], g_wsh1lo[36 * 1024];
__device__ __align__(16) __nv_bfloat16 g_wsh2hi[72 * 1024], g_wsh2lo[72 * 1024];
__device__ __align__(16) __nv_bfloat16 g_wdy1hi[(size_t)512 * 36 * 1024];
__device__ __align__(16) __nv_bfloat16 g_wdy1lo[(size_t)512 * 36 * 1024];
__device__ __align__(16) __nv_bfloat16 g_wdy2hi[(size_t)512 * 72 * 1024];
__device__ __align__(16) __nv_bfloat16 g_wdy2lo[(size_t)512 * 72 * 1024];

// ---------------- helpers -------------------------------------------------------
__device__ __forceinline__ uint32_t smem_u32(const void* p) {
    uint32_t a;
    asm("{ .reg .u64 t; cvta.to.shared.u64 t, %1; cvt.u32.u64 %0, t; }"
        : "=r"(a) : "l"(p));
    return a;
}
#define LDM4(r, a) \
    asm volatile("ldmatrix.sync.aligned.m8n8.x4.shared.b16 {%0,%1,%2,%3}, [%4];" \
                 : "=r"((r)[0]), "=r"((r)[1]), "=r"((r)[2]), "=r"((r)[3]) : "r"(a))
#define MMA(d, a, b0, b1) \
    asm volatile("mma.sync.aligned.m16n8k16.row.col.f32.bf16.bf16.f32 " \
                 "{%0,%1,%2,%3},{%4,%5,%6,%7},{%8,%9},{%0,%1,%2,%3};" \
                 : "+f"((d)[0]), "+f"((d)[1]), "+f"((d)[2]), "+f"((d)[3]) \
                 : "r"((a)[0]), "r"((a)[1]), "r"((a)[2]), "r"((a)[3]), "r"(b0), "r"(b1))

__device__ __forceinline__ uint32_t pkbf(float lo, float hi) {
    return (uint32_t)__bfloat16_as_ushort(__float2bfloat16(lo)) |
           ((uint32_t)__bfloat16_as_ushort(__float2bfloat16(hi)) << 16);
}

// single-buffer static smem: A halo hi/lo (136 rows x 48B), W_HI (3 taps x 128 x 48B)
static constexpr int S_AHI = 0;
static constexpr int S_ALO = 6528;      // 136*48
static constexpr int S_WHI = 13056;
static constexpr int SMEM_TOTAL = 31488; // + 3*128*48

// ---------------- small kernels -------------------------------------------------
__global__ void zero_stats_kernel() {
    int t = threadIdx.x;
    if (t < 128) { g_sum1[t] = 0.f; g_sqs1[t] = 0.f; g_sum2[t] = 0.f; g_sqs2[t] = 0.f; }
}

__global__ void zero_border_kernel() {
    int idx = blockIdx.x * 256 + threadIdx.x;
    if (idx >= 8 * 1028) return;
    int b = idx / 1028, s = idx % 1028;
    int y, x;
    if (s < 258)      { y = 0;           x = s; }
    else if (s < 516) { y = 257;         x = s - 258; }
    else if (s < 772) { y = s - 516 + 1; x = 0; }
    else              { y = s - 772 + 1; x = 257; }
    size_t p = ((size_t)b * PW + y) * PW + x;
    uint4 z = make_uint4(0, 0, 0, 0);
    uint4* h1 = (uint4*)(g_x1hi + p * 64);
    uint4* l1 = (uint4*)(g_x1lo + p * 64);
    #pragma unroll
    for (int i = 0; i < 8; ++i) { h1[i] = z; l1[i] = z; }
    uint4* h2 = (uint4*)(g_x2hi + p * 128);
    uint4* l2 = (uint4*)(g_x2lo + p * 128);
    #pragma unroll
    for (int i = 0; i < 16; ++i) { h2[i] = z; l2[i] = z; }
}

// x -> padded [b][y+1][x+1][ci] bf16 hi/lo; layer 2 applies BN1+ReLU
template<int CIN, int LAYER>
__global__ void xsplit_kernel(const float* __restrict__ xin)
{
    __shared__ float tile[CIN][65];
    const int blk = blockIdx.x;
    const int xb = blk & 3, y = (blk >> 2) & 255, b = blk >> 10;
    const int tid = threadIdx.x;
    const float* src = (LAYER == 1) ? xin : (const float*)g_y1;
    __nv_bfloat16* dhi = (LAYER == 1) ? g_x1hi : g_x2hi;
    __nv_bfloat16* dlo = (LAYER == 1) ? g_x1lo : g_x2lo;

    for (int i = tid; i < CIN * 64; i += 256) {
        int c = i >> 6, x = i & 63;
        float v = src[(((size_t)(b * CIN + c)) << 16) + (y << 8) + (xb << 6) + x];
        if (LAYER == 2) v = fmaxf(0.f, fmaf(g_a1[c], v, g_b1[c]));
        tile[c][x] = v;
    }
    __syncthreads();

    const int GSH = (CIN == 64) ? 3 : 4;
    const int GP  = CIN / 8;
    for (int i = tid; i < 64 * GP; i += 256) {
        int x = i >> GSH, g = i & (GP - 1);
        float v[8], hv[8];
        #pragma unroll
        for (int j = 0; j < 8; ++j) {
            v[j]  = tile[g * 8 + j][x];
            hv[j] = __bfloat162float(__float2bfloat16(v[j]));
        }
        uint4 uh, ul;
        uh.x = pkbf(hv[0], hv[1]); uh.y = pkbf(hv[2], hv[3]);
        uh.z = pkbf(hv[4], hv[5]); uh.w = pkbf(hv[6], hv[7]);
        ul.x = pkbf(v[0] - hv[0], v[1] - hv[1]); ul.y = pkbf(v[2] - hv[2], v[3] - hv[3]);
        ul.z = pkbf(v[4] - hv[4], v[5] - hv[5]); ul.w = pkbf(v[6] - hv[6], v[7] - hv[7]);
        size_t off = (((size_t)b * PW + (y + 1)) * PW + (xb * 64 + x + 1)) * CIN + g * 8;
        *(uint4*)((char*)dhi + off * 2) = uh;
        *(uint4*)((char*)dlo + off * 2) = ul;
    }
}

// shared weights [64oc][CIN][9] -> tiles [k*NS+sub][64][16]
template<int CIN, int LAYER>
__global__ void wprep_sh_kernel(const float* __restrict__ wsh)
{
    int idx = blockIdx.x * 256 + threadIdx.x;
    if (idx >= 64 * CIN) return;
    int ci = idx & (CIN - 1);
    int oc = idx >> ((CIN == 64) ? 6 : 7);
    constexpr int NS = CIN / 16;
    int sub = ci >> 4, cl = ci & 15;
    const float* s = wsh + ((size_t)oc * CIN + ci) * 9;
    __nv_bfloat16* hi = (LAYER == 1) ? g_wsh1hi : g_wsh2hi;
    __nv_bfloat16* lo = (LAYER == 1) ? g_wsh1lo : g_wsh2lo;
    #pragma unroll
    for (int k = 0; k < 9; ++k) {
        float v = s[k];
        __nv_bfloat16 hb = __float2bfloat16(v);
        size_t off = (size_t)(k * NS + sub) * 1024 + oc * 16 + cl;
        hi[off] = hb;
        lo[off] = __float2bfloat16(v - __bfloat162float(hb));
    }
}

// dynamic weights -> tiles [bp][k*NS+sub][64][16]
template<int CIN, int WOFF, int LAYER>
__global__ void wprep_dy_kernel(const float* __restrict__ cw)
{
    const long long idx = (long long)blockIdx.x * 256 + threadIdx.x;
    constexpr int LC = (CIN == 64) ? 6 : 7;
    const int ci = (int)(idx & (CIN - 1));
    const int oc = (int)((idx >> LC) & 63);
    const int bp = (int)(idx >> (LC + 6));
    constexpr int NS = CIN / 16;
    const int sub = ci >> 4, cl = ci & 15;
    const float* s = cw + (size_t)bp * ABLK + WOFF + ((size_t)oc * CIN + ci) * 9;
    __nv_bfloat16* hi = (LAYER == 1) ? g_wdy1hi : g_wdy2hi;
    __nv_bfloat16* lo = (LAYER == 1) ? g_wdy1lo : g_wdy2lo;
    #pragma unroll
    for (int k = 0; k < 9; ++k) {
        float v = s[k];
        __nv_bfloat16 hb = __float2bfloat16(v);
        size_t off = ((size_t)bp * (9 * NS) + k * NS + sub) * 1024 + oc * 16 + cl;
        hi[off] = hb;
        lo[off] = __float2bfloat16(v - __bfloat162float(hb));
    }
}

// ---------------- main conv: bf16-split warp-MMA, kx-tap halo reuse --------------
// CTA = (b, patch, 4-row quad). D[128 px][128 oc]; 8 warps x (64px x 32oc).
// Fill per (ky, ci-sub): A halo 4x34 px (hi/lo) + W_HI for 3 kx taps -> 3 taps of
// MMAs per fill. W_LO fragments read directly from gmem (L2-resident tiles).
template<int CIN, int LAYER>
__global__ void __launch_bounds__(256, 2)
conv_mma_kernel(float* __restrict__ dout)
{
    __shared__ __align__(16) unsigned char sm[SMEM_TOTAL];
    const uint32_t sbase = smem_u32(sm);
    const int tid = threadIdx.x, lane = tid & 31, wid = tid >> 5;
    const int wm = wid & 1, wn = wid >> 1;

    const __nv_bfloat16* xhi = (LAYER == 1) ? g_x1hi : g_x2hi;
    const __nv_bfloat16* xlo = (LAYER == 1) ? g_x1lo : g_x2lo;
    const __nv_bfloat16* wshhi = (LAYER == 1) ? g_wsh1hi : g_wsh2hi;
    const __nv_bfloat16* wshlo = (LAYER == 1) ? g_wsh1lo : g_wsh2lo;
    const __nv_bfloat16* wdyhi = (LAYER == 1) ? g_wdy1hi : g_wdy2hi;
    const __nv_bfloat16* wdylo = (LAYER == 1) ? g_wdy1lo : g_wdy2lo;
    float* dst = (LAYER == 1) ? (float*)g_y1 : dout;

    const int blk = blockIdx.x;
    const int b = blk >> 9, p = (blk >> 3) & 63, q = blk & 7;
    const int y0 = ((p >> 3) << 5) + (q << 2);
    const int x0 = (p & 7) << 5;
    const int bp = b * 64 + p;
    constexpr int NS = CIN / 16;

    float d[4][4][4];
    #pragma unroll
    for (int i = 0; i < 4; ++i)
        #pragma unroll
        for (int j = 0; j < 4; ++j)
            #pragma unroll
            for (int k = 0; k < 4; ++k) d[i][j][k] = 0.f;

    const uint32_t laneAoff = (uint32_t)(lane & 15) * 48 + (uint32_t)(lane >> 4) * 16;
    const uint32_t laneW = (uint32_t)((lane & 7) + ((lane >> 4) << 3)) * 48 +
                           (uint32_t)((lane >> 3) & 1) * 16;
    const int g8 = lane >> 2, t4 = lane & 3;
    const int wrow0 = (wn & 1) * 32 + g8;            // W_LO fragment oc-row base
    const __nv_bfloat16* wlo = (wn < 2) ? wshlo : wdylo;

    for (int f = 0; f < 3 * NS; ++f) {
        const int ky = f / NS, sub = f - ky * NS;
        __syncthreads();                             // prior compute done with smem
        // ---- fill A halo: 136 rows (4 x 34), hi+lo ----
        for (int i = tid; i < 544; i += 256) {
            int half = (i >= 272);
            int rr = half ? i - 272 : i;
            int r = rr >> 1, seg = rr & 1;
            int hy = r / 34, hx = r - hy * 34;
            size_t go = (((size_t)b * PW + (y0 + ky + hy)) * PW + (x0 + hx)) * CIN
                        + sub * 16 + seg * 8;
            const uint4* gp = (const uint4*)((half ? xlo : xhi) + go);
            *(uint4*)(sm + (half ? S_ALO : S_AHI) + r * 48 + seg * 16) = *gp;
        }
        // ---- fill W_HI: 3 taps x 128 oc rows x 32B ----
        for (int i = tid; i < 768; i += 256) {
            int tapk = i >> 8;
            int rr = i & 255;
            int row = rr >> 1, seg = rr & 1;
            const __nv_bfloat16* gp = (row < 64)
                ? wshhi + (size_t)((ky * 3 + tapk) * NS + sub) * 1024 + row * 16 + seg * 8
                : wdyhi + ((size_t)(bp * 9 + ky * 3 + tapk) * NS + sub) * 1024
                        + (row - 64) * 16 + seg * 8;
            *(uint4*)(sm + S_WHI + tapk * 6144 + row * 48 + seg * 16) = *(const uint4*)gp;
        }
        __syncthreads();

        // ---- compute 3 kx taps from this fill ----
        #pragma unroll
        for (int kx = 0; kx < 3; ++kx) {
            uint32_t a[4][4], w[2][4];
            #pragma unroll
            for (int mf = 0; mf < 4; ++mf) {
                int rb = ((wm * 2 + (mf >> 1)) * 34 + (mf & 1) * 16 + kx) * 48;
                LDM4(a[mf], sbase + S_AHI + rb + laneAoff);
            }
            #pragma unroll
            for (int nf = 0; nf < 2; ++nf)
                LDM4(w[nf], sbase + S_WHI + kx * 6144 + wn * 1536 + nf * 768 + laneW);
            // W_LO fragments straight from gmem (hidden under MMAs below)
            uint32_t v0[4], v1[4];
            {
                size_t t = (wn < 2)
                    ? (size_t)((ky * 3 + kx) * NS + sub)
                    : ((size_t)(bp * 9 + ky * 3 + kx) * NS + sub);
                const __nv_bfloat16* wb = wlo + t * 1024;
                #pragma unroll
                for (int j = 0; j < 4; ++j) {
                    const __nv_bfloat16* wp = wb + (wrow0 + j * 8) * 16 + t4 * 2;
                    v0[j] = *(const uint32_t*)(wp);
                    v1[j] = *(const uint32_t*)(wp + 8);
                }
            }
            // Ah * Wh
            #pragma unroll
            for (int mf = 0; mf < 4; ++mf)
                #pragma unroll
                for (int nf = 0; nf < 2; ++nf) {
                    MMA(d[mf][nf * 2],     a[mf], w[nf][0], w[nf][1]);
                    MMA(d[mf][nf * 2 + 1], a[mf], w[nf][2], w[nf][3]);
                }
            // Ah * Wl
            #pragma unroll
            for (int mf = 0; mf < 4; ++mf)
                #pragma unroll
                for (int j = 0; j < 4; ++j)
                    MMA(d[mf][j], a[mf], v0[j], v1[j]);
            // Al * Wh
            #pragma unroll
            for (int mf = 0; mf < 4; ++mf) {
                int rb = ((wm * 2 + (mf >> 1)) * 34 + (mf & 1) * 16 + kx) * 48;
                LDM4(a[mf], sbase + S_ALO + rb + laneAoff);
            }
            #pragma unroll
            for (int mf = 0; mf < 4; ++mf)
                #pragma unroll
                for (int nf = 0; nf < 2; ++nf) {
                    MMA(d[mf][nf * 2],     a[mf], w[nf][0], w[nf][1]);
                    MMA(d[mf][nf * 2 + 1], a[mf], w[nf][2], w[nf][3]);
                }
        }
    }

    // ---- epilogue: store + fused BN stats ----
    float* gsum = (LAYER == 1) ? g_sum1 : g_sum2;
    float* gsqs = (LAYER == 1) ? g_sqs1 : g_sqs2;
    const int r4 = lane >> 2;
    const int c2 = (lane & 3) << 1;
    #pragma unroll
    for (int mf = 0; mf < 4; ++mf) {
        int pxA = wm * 64 + mf * 16 + r4;
        int pxB = pxA + 8;
        size_t pixA = (size_t)(y0 + (pxA >> 5)) * 256 + x0 + (pxA & 31);
        size_t pixB = (size_t)(y0 + (pxB >> 5)) * 256 + x0 + (pxB & 31);
        #pragma unroll
        for (int n8 = 0; n8 < 4; ++n8) {
            int oc = wn * 32 + n8 * 8 + c2;
            size_t base = ((size_t)(b * 128 + oc)) << 16;
            dst[base + pixA]         = d[mf][n8][0];
            dst[base + 65536 + pixA] = d[mf][n8][1];
            dst[base + pixB]         = d[mf][n8][2];
            dst[base + 65536 + pixB] = d[mf][n8][3];
        }
    }
    #pragma unroll
    for (int n8 = 0; n8 < 4; ++n8) {
        float sA = 0.f, qA = 0.f, sB = 0.f, qB = 0.f;
        #pragma unroll
        for (int mf = 0; mf < 4; ++mf) {
            float e0 = d[mf][n8][0], e1 = d[mf][n8][1];
            float e2 = d[mf][n8][2], e3 = d[mf][n8][3];
            sA += e0 + e2; qA = fmaf(e0, e0, fmaf(e2, e2, qA));
            sB += e1 + e3; qB = fmaf(e1, e1, fmaf(e3, e3, qB));
        }
        #pragma unroll
        for (int off = 16; off >= 4; off >>= 1) {
            sA += __shfl_down_sync(0xffffffffu, sA, off);
            qA += __shfl_down_sync(0xffffffffu, qA, off);
            sB += __shfl_down_sync(0xffffffffu, sB, off);
            qB += __shfl_down_sync(0xffffffffu, qB, off);
        }
        if (lane < 4) {
            int oc = wn * 32 + n8 * 8 + c2;
            atomicAdd(&gsum[oc], sA);     atomicAdd(&gsqs[oc], qA);
            atomicAdd(&gsum[oc + 1], sB); atomicAdd(&gsqs[oc + 1], qB);
        }
    }
}

// ---------------- BN finalize / apply -------------------------------------------
__global__ void finalize_stats_kernel(const float* __restrict__ gamma,
                                      const float* __restrict__ beta, int layer)
{
    int c = threadIdx.x;
    if (c >= 128) return;
    const float invN = 1.f / (float)((size_t)BATCH * 256 * 256);
    float s = (layer == 1) ? g_sum1[c] : g_sum2[c];
    float q = (layer == 1) ? g_sqs1[c] : g_sqs2[c];
    float m = s * invN;
    float var = fmaf(-m, m, q * invN);
    float inv = rsqrtf(var + EPSBN);
    float a = gamma[c] * inv;
    float bb = fmaf(-a, m, beta[c]);
    if (layer == 1) { g_a1[c] = a; g_b1[c] = bb; }
    else            { g_a2[c] = a; g_b2[c] = bb; }
}

__global__ void apply_bn2_kernel(float4* __restrict__ out)
{
    const size_t n4 = (size_t)BATCH * 128 * 256 * 256 / 4;
    for (size_t i = (size_t)blockIdx.x * blockDim.x + threadIdx.x; i < n4;
         i += (size_t)gridDim.x * blockDim.x) {
        int c = (int)((i >> 14) & 127);
        float a = g_a2[c], bb = g_b2[c];
        float4 v = out[i];
        v.x = fmaxf(0.f, fmaf(a, v.x, bb));
        v.y = fmaxf(0.f, fmaf(a, v.y, bb));
        v.z = fmaxf(0.f, fmaf(a, v.z, bb));
        v.w = fmaxf(0.f, fmaf(a, v.w, bb));
        out[i] = v;
    }
}

// ---------------- launcher (harness pointers ONLY as kernel args) ----------------
extern "C" void kernel_launch(void* const* d_in, const int* in_sizes, int n_in,
                              void* d_out, int out_size)
{
    const float* x      = (const float*)d_in[0];
    const float* cw     = (const float*)d_in[1];
    const float* w1     = (const float*)d_in[2];
    const float* w2     = (const float*)d_in[3];
    const float* gamma1 = (const float*)d_in[4];
    const float* beta1  = (const float*)d_in[5];
    const float* gamma2 = (const float*)d_in[6];
    const float* beta2  = (const float*)d_in[7];
    float* out = (float*)d_out;

    zero_stats_kernel<<<1, 128>>>();
    zero_border_kernel<<<33, 256>>>();
    wprep_sh_kernel<64, 1><<<16, 256>>>(w1);
    wprep_sh_kernel<128, 2><<<32, 256>>>(w2);
    wprep_dy_kernel<64, 0, 1><<<8192, 256>>>(cw);
    wprep_dy_kernel<128, WOFF2, 2><<<16384, 256>>>(cw);

    // layer 1
    xsplit_kernel<64, 1><<<8192, 256>>>(x);
    conv_mma_kernel<64, 1><<<4096, 256>>>(nullptr);
    finalize_stats_kernel<<<1, 128>>>(gamma1, beta1, 1);

    // layer 2 (BN1+ReLU fused into xsplit)
    xsplit_kernel<128, 2><<<8192, 256>>>(nullptr);
    conv_mma_kernel<128, 2><<<4096, 256>>>(out);
    finalize_stats_kernel<<<1, 128>>>(gamma2, beta2, 2);

    apply_bn2_kernel<<<8192, 256>>>((float4*)out);
}

// round 16
// speedup vs baseline: 1.1493x; 1.0286x over previous
#include <cuda_runtime.h>
#include <cuda_bf16.h>
#include <cstdint>

#define BATCH 8
#define EPSBN 1e-5f
#define ABLK  110592
#define WOFF2 36864
#define PW    258            // padded width (1-px halo each side)

// ---------------- scratch globals (all referenced ONLY in device code) ----------
__device__ float g_y1[(size_t)8 * 128 * 256 * 256];            // 256 MB
__device__ float g_sum1[128], g_sqs1[128], g_sum2[128], g_sqs2[128];
__device__ float g_a1[128], g_b1[128], g_a2[128], g_b2[128];

// padded split activations [b][y+1][x+1][ci] bf16
__device__ __align__(16) __nv_bfloat16 g_x1hi[(size_t)8 * PW * PW * 64];
__device__ __align__(16) __nv_bfloat16 g_x1lo[(size_t)8 * PW * PW * 64];
__device__ __align__(16) __nv_bfloat16 g_x2hi[(size_t)8 * PW * PW * 128];
__device__ __align__(16) __nv_bfloat16 g_x2lo[(size_t)8 * PW * PW * 128];
// weight tiles, k-chunk 16: [(k*NS)+sub][64 oc][16 ci]
__device__ __align__(16) __nv_bfloat16 g_wsh1hi[36 * 1024], g_wsh1lo[36 * 1024];
__device__ __align__(16) __nv_bfloat16 g_wsh2hi[72 * 1024], g_wsh2lo[72 * 1024];
__device__ __align__(16) __nv_bfloat16 g_wdy1hi[(size_t)512 * 36 * 1024];
__device__ __align__(16) __nv_bfloat16 g_wdy1lo[(size_t)512 * 36 * 1024];
__device__ __align__(16) __nv_bfloat16 g_wdy2hi[(size_t)512 * 72 * 1024];
__device__ __align__(16) __nv_bfloat16 g_wdy2lo[(size_t)512 * 72 * 1024];

// ---------------- helpers -------------------------------------------------------
__device__ __forceinline__ uint32_t smem_u32(const void* p) {
    uint32_t a;
    asm("{ .reg .u64 t; cvta.to.shared.u64 t, %1; cvt.u32.u64 %0, t; }"
        : "=r"(a) : "l"(p));
    return a;
}
#define CPA(dst, src) \
    asm volatile("cp.async.cg.shared.global [%0], [%1], 16;" \
                 :: "r"((uint32_t)(dst)), "l"(src) : "memory")
#define CPCOMMIT() asm volatile("cp.async.commit_group;" ::: "memory")
#define CPWAIT1()  asm volatile("cp.async.wait_group 1;" ::: "memory")
#define CPWAIT0()  asm volatile("cp.async.wait_group 0;" ::: "memory")
#define LDM4(r, a) \
    asm volatile("ldmatrix.sync.aligned.m8n8.x4.shared.b16 {%0,%1,%2,%3}, [%4];" \
                 : "=r"((r)[0]), "=r"((r)[1]), "=r"((r)[2]), "=r"((r)[3]) : "r"(a))
#define MMA(d, a, b0, b1) \
    asm volatile("mma.sync.aligned.m16n8k16.row.col.f32.bf16.bf16.f32 " \
                 "{%0,%1,%2,%3},{%4,%5,%6,%7},{%8,%9},{%0,%1,%2,%3};" \
                 : "+f"((d)[0]), "+f"((d)[1]), "+f"((d)[2]), "+f"((d)[3]) \
                 : "r"((a)[0]), "r"((a)[1]), "r"((a)[2]), "r"((a)[3]), "r"(b0), "r"(b1))

__device__ __forceinline__ uint32_t pkbf(float lo, float hi) {
    return (uint32_t)__bfloat16_as_ushort(__float2bfloat16(lo)) |
           ((uint32_t)__bfloat16_as_ushort(__float2bfloat16(hi)) << 16);
}

// 3-stage ring in dynamic smem: per stage A_HI/A_LO/W_HI/W_LO, 128 rows x 48B each
static constexpr int S_ALO   = 6144;
static constexpr int S_WHI   = 12288;
static constexpr int S_WLO   = 18432;
static constexpr int S_STAGE = 24576;
static constexpr int NSTAGE  = 3;
static constexpr int SMEM_TOTAL = S_STAGE * NSTAGE;   // 73728 B dynamic

// ---------------- small kernels -------------------------------------------------
__global__ void zero_stats_kernel() {
    int t = threadIdx.x;
    if (t < 128) { g_sum1[t] = 0.f; g_sqs1[t] = 0.f; g_sum2[t] = 0.f; g_sqs2[t] = 0.f; }
}

__global__ void zero_border_kernel() {
    int idx = blockIdx.x * 256 + threadIdx.x;
    if (idx >= 8 * 1028) return;
    int b = idx / 1028, s = idx % 1028;
    int y, x;
    if (s < 258)      { y = 0;           x = s; }
    else if (s < 516) { y = 257;         x = s - 258; }
    else if (s < 772) { y = s - 516 + 1; x = 0; }
    else              { y = s - 772 + 1; x = 257; }
    size_t p = ((size_t)b * PW + y) * PW + x;
    uint4 z = make_uint4(0, 0, 0, 0);
    uint4* h1 = (uint4*)(g_x1hi + p * 64);
    uint4* l1 = (uint4*)(g_x1lo + p * 64);
    #pragma unroll
    for (int i = 0; i < 8; ++i) { h1[i] = z; l1[i] = z; }
    uint4* h2 = (uint4*)(g_x2hi + p * 128);
    uint4* l2 = (uint4*)(g_x2lo + p * 128);
    #pragma unroll
    for (int i = 0; i < 16; ++i) { h2[i] = z; l2[i] = z; }
}

// x -> padded [b][y+1][x+1][ci] bf16 hi/lo; layer 2 applies BN1+ReLU
template<int CIN, int LAYER>
__global__ void xsplit_kernel(const float* __restrict__ xin)
{
    __shared__ float tile[CIN][65];
    const int blk = blockIdx.x;
    const int xb = blk & 3, y = (blk >> 2) & 255, b = blk >> 10;
    const int tid = threadIdx.x;
    const float* src = (LAYER == 1) ? xin : (const float*)g_y1;
    __nv_bfloat16* dhi = (LAYER == 1) ? g_x1hi : g_x2hi;
    __nv_bfloat16* dlo = (LAYER == 1) ? g_x1lo : g_x2lo;

    for (int i = tid; i < CIN * 64; i += 256) {
        int c = i >> 6, x = i & 63;
        float v = src[(((size_t)(b * CIN + c)) << 16) + (y << 8) + (xb << 6) + x];
        if (LAYER == 2) v = fmaxf(0.f, fmaf(g_a1[c], v, g_b1[c]));
        tile[c][x] = v;
    }
    __syncthreads();

    const int GSH = (CIN == 64) ? 3 : 4;
    const int GP  = CIN / 8;
    for (int i = tid; i < 64 * GP; i += 256) {
        int x = i >> GSH, g = i & (GP - 1);
        float v[8], hv[8];
        #pragma unroll
        for (int j = 0; j < 8; ++j) {
            v[j]  = tile[g * 8 + j][x];
            hv[j] = __bfloat162float(__float2bfloat16(v[j]));
        }
        uint4 uh, ul;
        uh.x = pkbf(hv[0], hv[1]); uh.y = pkbf(hv[2], hv[3]);
        uh.z = pkbf(hv[4], hv[5]); uh.w = pkbf(hv[6], hv[7]);
        ul.x = pkbf(v[0] - hv[0], v[1] - hv[1]); ul.y = pkbf(v[2] - hv[2], v[3] - hv[3]);
        ul.z = pkbf(v[4] - hv[4], v[5] - hv[5]); ul.w = pkbf(v[6] - hv[6], v[7] - hv[7]);
        size_t off = (((size_t)b * PW + (y + 1)) * PW + (xb * 64 + x + 1)) * CIN + g * 8;
        *(uint4*)((char*)dhi + off * 2) = uh;
        *(uint4*)((char*)dlo + off * 2) = ul;
    }
}

// shared weights [64oc][CIN][9] -> tiles [k*NS+sub][64][16]
template<int CIN, int LAYER>
__global__ void wprep_sh_kernel(const float* __restrict__ wsh)
{
    int idx = blockIdx.x * 256 + threadIdx.x;
    if (idx >= 64 * CIN) return;
    int ci = idx & (CIN - 1);
    int oc = idx >> ((CIN == 64) ? 6 : 7);
    constexpr int NS = CIN / 16;
    int sub = ci >> 4, cl = ci & 15;
    const float* s = wsh + ((size_t)oc * CIN + ci) * 9;
    __nv_bfloat16* hi = (LAYER == 1) ? g_wsh1hi : g_wsh2hi;
    __nv_bfloat16* lo = (LAYER == 1) ? g_wsh1lo : g_wsh2lo;
    #pragma unroll
    for (int k = 0; k < 9; ++k) {
        float v = s[k];
        __nv_bfloat16 hb = __float2bfloat16(v);
        size_t off = (size_t)(k * NS + sub) * 1024 + oc * 16 + cl;
        hi[off] = hb;
        lo[off] = __float2bfloat16(v - __bfloat162float(hb));
    }
}

// dynamic weights -> tiles [bp][k*NS+sub][64][16]
template<int CIN, int WOFF, int LAYER>
__global__ void wprep_dy_kernel(const float* __restrict__ cw)
{
    const long long idx = (long long)blockIdx.x * 256 + threadIdx.x;
    constexpr int LC = (CIN == 64) ? 6 : 7;
    const int ci = (int)(idx & (CIN - 1));
    const int oc = (int)((idx >> LC) & 63);
    const int bp = (int)(idx >> (LC + 6));
    constexpr int NS = CIN / 16;
    const int sub = ci >> 4, cl = ci & 15;
    const float* s = cw + (size_t)bp * ABLK + WOFF + ((size_t)oc * CIN + ci) * 9;
    __nv_bfloat16* hi = (LAYER == 1) ? g_wdy1hi : g_wdy2hi;
    __nv_bfloat16* lo = (LAYER == 1) ? g_wdy1lo : g_wdy2lo;
    #pragma unroll
    for (int k = 0; k < 9; ++k) {
        float v = s[k];
        __nv_bfloat16 hb = __float2bfloat16(v);
        size_t off = ((size_t)bp * (9 * NS) + k * NS + sub) * 1024 + oc * 16 + cl;
        hi[off] = hb;
        lo[off] = __float2bfloat16(v - __bfloat162float(hb));
    }
}

// ---------------- main conv: bf16-split warp-MMA, 3-stage cp.async ring ----------
// CTA = (b, patch, 4-row quad). D[128 px][128 oc]; 8 warps x (64px x 32oc).
// One __syncthreads per chunk; loads issued 2 chunks ahead via cp.async.
template<int CIN, int LAYER>
__global__ void __launch_bounds__(256, 2)
conv_mma_kernel(float* __restrict__ dout)
{
    extern __shared__ __align__(16) unsigned char sm[];
    const uint32_t sbase = smem_u32(sm);
    const int tid = threadIdx.x, lane = tid & 31, wid = tid >> 5;
    const int wm = wid & 1, wn = wid >> 1;

    const __nv_bfloat16* xhi = (LAYER == 1) ? g_x1hi : g_x2hi;
    const __nv_bfloat16* xlo = (LAYER == 1) ? g_x1lo : g_x2lo;
    const __nv_bfloat16* wshhi = (LAYER == 1) ? g_wsh1hi : g_wsh2hi;
    const __nv_bfloat16* wshlo = (LAYER == 1) ? g_wsh1lo : g_wsh2lo;
    const __nv_bfloat16* wdyhi = (LAYER == 1) ? g_wdy1hi : g_wdy2hi;
    const __nv_bfloat16* wdylo = (LAYER == 1) ? g_wdy1lo : g_wdy2lo;
    float* dst = (LAYER == 1) ? (float*)g_y1 : dout;

    const int blk = blockIdx.x;
    const int b = blk >> 9, p = (blk >> 3) & 63, q = blk & 7;
    const int y0 = ((p >> 3) << 5) + (q << 2);
    const int x0 = (p & 7) << 5;
    const int bp = b * 64 + p;
    constexpr int NS = CIN / 16;
    constexpr int NC = 9 * NS;

    float d[4][4][4];
    #pragma unroll
    for (int i = 0; i < 4; ++i)
        #pragma unroll
        for (int j = 0; j < 4; ++j)
            #pragma unroll
            for (int k = 0; k < 4; ++k) d[i][j][k] = 0.f;

    const uint32_t laneA = (uint32_t)(lane & 15) * 48 + (uint32_t)(lane >> 4) * 16;
    const uint32_t laneW = (uint32_t)((lane & 7) + ((lane >> 4) << 3)) * 48 +
                           (uint32_t)((lane >> 3) & 1) * 16;

    const int px = tid >> 1, seg = tid & 1;    // A row / 16B seg
    const int wrow = tid >> 1;                 // W row

    auto issue = [&](int cc, int stage) {
        const int tap = cc / NS, sub = cc - tap * NS;
        const int ky = tap / 3, kx = tap - ky * 3;
        const uint32_t sb = sbase + stage * S_STAGE;
        const int y = y0 + (px >> 5) + ky;
        const int x = x0 + (px & 31) + kx;
        const size_t aoff = (((size_t)b * PW + y) * PW + x) * CIN + sub * 16 + seg * 8;
        CPA(sb + px * 48 + seg * 16, (const char*)(xhi + aoff));
        CPA(sb + S_ALO + px * 48 + seg * 16, (const char*)(xlo + aoff));
        if (wrow < 64) {
            const size_t woff = (size_t)cc * 1024 + wrow * 16 + seg * 8;
            CPA(sb + S_WHI + wrow * 48 + seg * 16, (const char*)(wshhi + woff));
            CPA(sb + S_WLO + wrow * 48 + seg * 16, (const char*)(wshlo + woff));
        } else {
            const size_t woff = ((size_t)bp * NC + cc) * 1024 + (wrow - 64) * 16 + seg * 8;
            CPA(sb + S_WHI + wrow * 48 + seg * 16, (const char*)(wdyhi + woff));
            CPA(sb + S_WLO + wrow * 48 + seg * 16, (const char*)(wdylo + woff));
        }
        CPCOMMIT();
    };

    issue(0, 0);
    issue(1, 1);

    for (int cc = 0; cc < NC; ++cc) {
        const int stage = cc % NSTAGE;
        if (cc + 1 < NC) CPWAIT1(); else CPWAIT0();  // chunk cc's group landed
        __syncthreads();                              // all warps past compute(cc-1)
        if (cc + 2 < NC) issue(cc + 2, (cc + 2) % NSTAGE);

        // ---- compute: D += Ah*Wh + Ah*Wl + Al*Wh ----
        const uint32_t sb = sbase + stage * S_STAGE;
        const uint32_t Ah = sb + wm * 3072 + laneA;
        const uint32_t Al = Ah + S_ALO;
        const uint32_t Wh = sb + S_WHI + wn * 1536 + laneW;
        const uint32_t Wl = Wh + 6144;
        uint32_t a[4][4], w[2][4], v[2][4];
        #pragma unroll
        for (int mf = 0; mf < 4; ++mf) LDM4(a[mf], Ah + mf * 768);
        #pragma unroll
        for (int nf = 0; nf < 2; ++nf) LDM4(w[nf], Wh + nf * 768);
        #pragma unroll
        for (int mf = 0; mf < 4; ++mf)
            #pragma unroll
            for (int nf = 0; nf < 2; ++nf) {
                MMA(d[mf][nf * 2],     a[mf], w[nf][0], w[nf][1]);
                MMA(d[mf][nf * 2 + 1], a[mf], w[nf][2], w[nf][3]);
            }
        #pragma unroll
        for (int nf = 0; nf < 2; ++nf) LDM4(v[nf], Wl + nf * 768);
        #pragma unroll
        for (int mf = 0; mf < 4; ++mf)
            #pragma unroll
            for (int nf = 0; nf < 2; ++nf) {
                MMA(d[mf][nf * 2],     a[mf], v[nf][0], v[nf][1]);
                MMA(d[mf][nf * 2 + 1], a[mf], v[nf][2], v[nf][3]);
            }
        #pragma unroll
        for (int mf = 0; mf < 4; ++mf) LDM4(a[mf], Al + mf * 768);
        #pragma unroll
        for (int mf = 0; mf < 4; ++mf)
            #pragma unroll
            for (int nf = 0; nf < 2; ++nf) {
                MMA(d[mf][nf * 2],     a[mf], w[nf][0], w[nf][1]);
                MMA(d[mf][nf * 2 + 1], a[mf], w[nf][2], w[nf][3]);
            }
    }

    // ---- epilogue: store + fused BN stats ----
    float* gsum = (LAYER == 1) ? g_sum1 : g_sum2;
    float* gsqs = (LAYER == 1) ? g_sqs1 : g_sqs2;
    const int r4 = lane >> 2;
    const int c2 = (lane & 3) << 1;
    #pragma unroll
    for (int mf = 0; mf < 4; ++mf) {
        int pxA = wm * 64 + mf * 16 + r4;
        int pxB = pxA + 8;
        size_t pixA = (size_t)(y0 + (pxA >> 5)) * 256 + x0 + (pxA & 31);
        size_t pixB = (size_t)(y0 + (pxB >> 5)) * 256 + x0 + (pxB & 31);
        #pragma unroll
        for (int n8 = 0; n8 < 4; ++n8) {
            int oc = wn * 32 + n8 * 8 + c2;
            size_t base = ((size_t)(b * 128 + oc)) << 16;
            dst[base + pixA]         = d[mf][n8][0];
            dst[base + 65536 + pixA] = d[mf][n8][1];
            dst[base + pixB]         = d[mf][n8][2];
            dst[base + 65536 + pixB] = d[mf][n8][3];
        }
    }
    #pragma unroll
    for (int n8 = 0; n8 < 4; ++n8) {
        float sA = 0.f, qA = 0.f, sB = 0.f, qB = 0.f;
        #pragma unroll
        for (int mf = 0; mf < 4; ++mf) {
            float e0 = d[mf][n8][0], e1 = d[mf][n8][1];
            float e2 = d[mf][n8][2], e3 = d[mf][n8][3];
            sA += e0 + e2; qA = fmaf(e0, e0, fmaf(e2, e2, qA));
            sB += e1 + e3; qB = fmaf(e1, e1, fmaf(e3, e3, qB));
        }
        #pragma unroll
        for (int off = 16; off >= 4; off >>= 1) {
            sA += __shfl_down_sync(0xffffffffu, sA, off);
            qA += __shfl_down_sync(0xffffffffu, qA, off);
            sB += __shfl_down_sync(0xffffffffu, sB, off);
            qB += __shfl_down_sync(0xffffffffu, qB, off);
        }
        if (lane < 4) {
            int oc = wn * 32 + n8 * 8 + c2;
            atomicAdd(&gsum[oc], sA);     atomicAdd(&gsqs[oc], qA);
            atomicAdd(&gsum[oc + 1], sB); atomicAdd(&gsqs[oc + 1], qB);
        }
    }
}

// ---------------- BN finalize / apply -------------------------------------------
__global__ void finalize_stats_kernel(const float* __restrict__ gamma,
                                      const float* __restrict__ beta, int layer)
{
    int c = threadIdx.x;
    if (c >= 128) return;
    const float invN = 1.f / (float)((size_t)BATCH * 256 * 256);
    float s = (layer == 1) ? g_sum1[c] : g_sum2[c];
    float q = (layer == 1) ? g_sqs1[c] : g_sqs2[c];
    float m = s * invN;
    float var = fmaf(-m, m, q * invN);
    float inv = rsqrtf(var + EPSBN);
    float a = gamma[c] * inv;
    float bb = fmaf(-a, m, beta[c]);
    if (layer == 1) { g_a1[c] = a; g_b1[c] = bb; }
    else            { g_a2[c] = a; g_b2[c] = bb; }
}

__global__ void apply_bn2_kernel(float4* __restrict__ out)
{
    const size_t n4 = (size_t)BATCH * 128 * 256 * 256 / 4;
    for (size_t i = (size_t)blockIdx.x * blockDim.x + threadIdx.x; i < n4;
         i += (size_t)gridDim.x * blockDim.x) {
        int c = (int)((i >> 14) & 127);
        float a = g_a2[c], bb = g_b2[c];
        float4 v = out[i];
        v.x = fmaxf(0.f, fmaf(a, v.x, bb));
        v.y = fmaxf(0.f, fmaf(a, v.y, bb));
        v.z = fmaxf(0.f, fmaf(a, v.z, bb));
        v.w = fmaxf(0.f, fmaf(a, v.w, bb));
        out[i] = v;
    }
}

// ---------------- launcher (harness pointers ONLY as kernel args) ----------------
extern "C" void kernel_launch(void* const* d_in, const int* in_sizes, int n_in,
                              void* d_out, int out_size)
{
    const float* x      = (const float*)d_in[0];
    const float* cw     = (const float*)d_in[1];
    const float* w1     = (const float*)d_in[2];
    const float* w2     = (const float*)d_in[3];
    const float* gamma1 = (const float*)d_in[4];
    const float* beta1  = (const float*)d_in[5];
    const float* gamma2 = (const float*)d_in[6];
    const float* beta2  = (const float*)d_in[7];
    float* out = (float*)d_out;

    cudaFuncSetAttribute(conv_mma_kernel<64, 1>,
                         cudaFuncAttributeMaxDynamicSharedMemorySize, SMEM_TOTAL);
    cudaFuncSetAttribute(conv_mma_kernel<128, 2>,
                         cudaFuncAttributeMaxDynamicSharedMemorySize, SMEM_TOTAL);

    zero_stats_kernel<<<1, 128>>>();
    zero_border_kernel<<<33, 256>>>();
    wprep_sh_kernel<64, 1><<<16, 256>>>(w1);
    wprep_sh_kernel<128, 2><<<32, 256>>>(w2);
    wprep_dy_kernel<64, 0, 1><<<8192, 256>>>(cw);
    wprep_dy_kernel<128, WOFF2, 2><<<16384, 256>>>(cw);

    // layer 1
    xsplit_kernel<64, 1><<<8192, 256>>>(x);
    conv_mma_kernel<64, 1><<<4096, 256, SMEM_TOTAL>>>(nullptr);
    finalize_stats_kernel<<<1, 128>>>(gamma1, beta1, 1);

    // layer 2 (BN1+ReLU fused into xsplit)
    xsplit_kernel<128, 2><<<8192, 256>>>(nullptr);
    conv_mma_kernel<128, 2><<<4096, 256, SMEM_TOTAL>>>(out);
    finalize_stats_kernel<<<1, 128>>>(gamma2, beta2, 2);

    apply_bn2_kernel<<<8192, 256>>>((float4*)out);
}

// round 17
// speedup vs baseline: 1.2824x; 1.1158x over previous
#include <cuda_runtime.h>
#include <cuda_bf16.h>
#include <cstdint>

#define BATCH 8
#define EPSBN 1e-5f
#define ABLK  110592
#define WOFF2 36864
#define PW    258            // padded width (1-px halo each side)

// ---------------- scratch globals (all referenced ONLY in device code) ----------
__device__ float g_y1[(size_t)8 * 128 * 256 * 256];            // 256 MB
__device__ float g_sum1[128], g_sqs1[128], g_sum2[128], g_sqs2[128];
__device__ float g_a1[128], g_b1[128], g_a2[128], g_b2[128];

// padded split activations [b][y+1][x+1][ci] bf16
__device__ __align__(16) __nv_bfloat16 g_x1hi[(size_t)8 * PW * PW * 64];
__device__ __align__(16) __nv_bfloat16 g_x1lo[(size_t)8 * PW * PW * 64];
__device__ __align__(16) __nv_bfloat16 g_x2hi[(size_t)8 * PW * PW * 128];
__device__ __align__(16) __nv_bfloat16 g_x2lo[(size_t)8 * PW * PW * 128];
// weight tiles, k-chunk 16: [(k*NS)+sub][64 oc][16 ci]
__device__ __align__(16) __nv_bfloat16 g_wsh1hi[36 * 1024], g_wsh1lo[36 * 1024];
__device__ __align__(16) __nv_bfloat16 g_wsh2hi[72 * 1024], g_wsh2lo[72 * 1024];
__device__ __align__(16) __nv_bfloat16 g_wdy1hi[(size_t)512 * 36 * 1024];
__device__ __align__(16) __nv_bfloat16 g_wdy1lo[(size_t)512 * 36 * 1024];
__device__ __align__(16) __nv_bfloat16 g_wdy2hi[(size_t)512 * 72 * 1024];
__device__ __align__(16) __nv_bfloat16 g_wdy2lo[(size_t)512 * 72 * 1024];

// ---------------- helpers -------------------------------------------------------
__device__ __forceinline__ uint32_t smem_u32(const void* p) {
    uint32_t a;
    asm("{ .reg .u64 t; cvta.to.shared.u64 t, %1; cvt.u32.u64 %0, t; }"
        : "=r"(a) : "l"(p));
    return a;
}
#define LDM4(r, a) \
    asm volatile("ldmatrix.sync.aligned.m8n8.x4.shared.b16 {%0,%1,%2,%3}, [%4];" \
                 : "=r"((r)[0]), "=r"((r)[1]), "=r"((r)[2]), "=r"((r)[3]) : "r"(a))
#define MMA(d, a, b0, b1) \
    asm volatile("mma.sync.aligned.m16n8k16.row.col.f32.bf16.bf16.f32 " \
                 "{%0,%1,%2,%3},{%4,%5,%6,%7},{%8,%9},{%0,%1,%2,%3};" \
                 : "+f"((d)[0]), "+f"((d)[1]), "+f"((d)[2]), "+f"((d)[3]) \
                 : "r"((a)[0]), "r"((a)[1]), "r"((a)[2]), "r"((a)[3]), "r"(b0), "r"(b1))

__device__ __forceinline__ uint32_t pkbf(float lo, float hi) {
    return (uint32_t)__bfloat16_as_ushort(__float2bfloat16(lo)) |
           ((uint32_t)__bfloat16_as_ushort(__float2bfloat16(hi)) << 16);
}

// double-buffered static smem: per buffer A_HI/A_LO/W_HI/W_LO, 128 rows x 48B each
static constexpr int S_ALO = 6144;
static constexpr int S_WHI = 12288;
static constexpr int S_WLO = 18432;
static constexpr int S_BUF = 24576;
static constexpr int SMEM_TOTAL = 49152;   // exactly 48KB static

// ---------------- small kernels -------------------------------------------------
__global__ void zero_stats_kernel() {
    int t = threadIdx.x;
    if (t < 128) { g_sum1[t] = 0.f; g_sqs1[t] = 0.f; g_sum2[t] = 0.f; g_sqs2[t] = 0.f; }
}

__global__ void zero_border_kernel() {
    int idx = blockIdx.x * 256 + threadIdx.x;
    if (idx >= 8 * 1028) return;
    int b = idx / 1028, s = idx % 1028;
    int y, x;
    if (s < 258)      { y = 0;           x = s; }
    else if (s < 516) { y = 257;         x = s - 258; }
    else if (s < 772) { y = s - 516 + 1; x = 0; }
    else              { y = s - 772 + 1; x = 257; }
    size_t p = ((size_t)b * PW + y) * PW + x;
    uint4 z = make_uint4(0, 0, 0, 0);
    uint4* h1 = (uint4*)(g_x1hi + p * 64);
    uint4* l1 = (uint4*)(g_x1lo + p * 64);
    #pragma unroll
    for (int i = 0; i < 8; ++i) { h1[i] = z; l1[i] = z; }
    uint4* h2 = (uint4*)(g_x2hi + p * 128);
    uint4* l2 = (uint4*)(g_x2lo + p * 128);
    #pragma unroll
    for (int i = 0; i < 16; ++i) { h2[i] = z; l2[i] = z; }
}

// x -> padded [b][y+1][x+1][ci] bf16 hi/lo; layer 2 applies BN1+ReLU
template<int CIN, int LAYER>
__global__ void xsplit_kernel(const float* __restrict__ xin)
{
    __shared__ float tile[CIN][65];
    const int blk = blockIdx.x;
    const int xb = blk & 3, y = (blk >> 2) & 255, b = blk >> 10;
    const int tid = threadIdx.x;
    const float* src = (LAYER == 1) ? xin : (const float*)g_y1;
    __nv_bfloat16* dhi = (LAYER == 1) ? g_x1hi : g_x2hi;
    __nv_bfloat16* dlo = (LAYER == 1) ? g_x1lo : g_x2lo;

    for (int i = tid; i < CIN * 64; i += 256) {
        int c = i >> 6, x = i & 63;
        float v = src[(((size_t)(b * CIN + c)) << 16) + (y << 8) + (xb << 6) + x];
        if (LAYER == 2) v = fmaxf(0.f, fmaf(g_a1[c], v, g_b1[c]));
        tile[c][x] = v;
    }
    __syncthreads();

    const int GSH = (CIN == 64) ? 3 : 4;
    const int GP  = CIN / 8;
    for (int i = tid; i < 64 * GP; i += 256) {
        int x = i >> GSH, g = i & (GP - 1);
        float v[8], hv[8];
        #pragma unroll
        for (int j = 0; j < 8; ++j) {
            v[j]  = tile[g * 8 + j][x];
            hv[j] = __bfloat162float(__float2bfloat16(v[j]));
        }
        uint4 uh, ul;
        uh.x = pkbf(hv[0], hv[1]); uh.y = pkbf(hv[2], hv[3]);
        uh.z = pkbf(hv[4], hv[5]); uh.w = pkbf(hv[6], hv[7]);
        ul.x = pkbf(v[0] - hv[0], v[1] - hv[1]); ul.y = pkbf(v[2] - hv[2], v[3] - hv[3]);
        ul.z = pkbf(v[4] - hv[4], v[5] - hv[5]); ul.w = pkbf(v[6] - hv[6], v[7] - hv[7]);
        size_t off = (((size_t)b * PW + (y + 1)) * PW + (xb * 64 + x + 1)) * CIN + g * 8;
        *(uint4*)((char*)dhi + off * 2) = uh;
        *(uint4*)((char*)dlo + off * 2) = ul;
    }
}

// shared weights [64oc][CIN][9] -> tiles [k*NS+sub][64][16]
template<int CIN, int LAYER>
__global__ void wprep_sh_kernel(const float* __restrict__ wsh)
{
    int idx = blockIdx.x * 256 + threadIdx.x;
    if (idx >= 64 * CIN) return;
    int ci = idx & (CIN - 1);
    int oc = idx >> ((CIN == 64) ? 6 : 7);
    constexpr int NS = CIN / 16;
    int sub = ci >> 4, cl = ci & 15;
    const float* s = wsh + ((size_t)oc * CIN + ci) * 9;
    __nv_bfloat16* hi = (LAYER == 1) ? g_wsh1hi : g_wsh2hi;
    __nv_bfloat16* lo = (LAYER == 1) ? g_wsh1lo : g_wsh2lo;
    #pragma unroll
    for (int k = 0; k < 9; ++k) {
        float v = s[k];
        __nv_bfloat16 hb = __float2bfloat16(v);
        size_t off = (size_t)(k * NS + sub) * 1024 + oc * 16 + cl;
        hi[off] = hb;
        lo[off] = __float2bfloat16(v - __bfloat162float(hb));
    }
}

// dynamic weights -> tiles [bp][k*NS+sub][64][16]
template<int CIN, int WOFF, int LAYER>
__global__ void wprep_dy_kernel(const float* __restrict__ cw)
{
    const long long idx = (long long)blockIdx.x * 256 + threadIdx.x;
    constexpr int LC = (CIN == 64) ? 6 : 7;
    const int ci = (int)(idx & (CIN - 1));
    const int oc = (int)((idx >> LC) & 63);
    const int bp = (int)(idx >> (LC + 6));
    constexpr int NS = CIN / 16;
    const int sub = ci >> 4, cl = ci & 15;
    const float* s = cw + (size_t)bp * ABLK + WOFF + ((size_t)oc * CIN + ci) * 9;
    __nv_bfloat16* hi = (LAYER == 1) ? g_wdy1hi : g_wdy2hi;
    __nv_bfloat16* lo = (LAYER == 1) ? g_wdy1lo : g_wdy2lo;
    #pragma unroll
    for (int k = 0; k < 9; ++k) {
        float v = s[k];
        __nv_bfloat16 hb = __float2bfloat16(v);
        size_t off = ((size_t)bp * (9 * NS) + k * NS + sub) * 1024 + oc * 16 + cl;
        hi[off] = hb;
        lo[off] = __float2bfloat16(v - __bfloat162float(hb));
    }
}

// ---------------- main conv: bf16-split warp-MMA, smem-double-buffered -----------
// CTA = (b, patch, 4-row quad). D[128 px][128 oc]; 8 warps x (64px x 32oc).
// Software-pipelined fragment loads: Al LDM4s hoisted under pass-2 MMAs.
template<int CIN, int LAYER>
__global__ void __launch_bounds__(256, 2)
conv_mma_kernel(float* __restrict__ dout)
{
    __shared__ __align__(16) unsigned char sm[SMEM_TOTAL];
    const uint32_t sbase = smem_u32(sm);
    const int tid = threadIdx.x, lane = tid & 31, wid = tid >> 5;
    const int wm = wid & 1, wn = wid >> 1;

    const __nv_bfloat16* xhi = (LAYER == 1) ? g_x1hi : g_x2hi;
    const __nv_bfloat16* xlo = (LAYER == 1) ? g_x1lo : g_x2lo;
    const __nv_bfloat16* wshhi = (LAYER == 1) ? g_wsh1hi : g_wsh2hi;
    const __nv_bfloat16* wshlo = (LAYER == 1) ? g_wsh1lo : g_wsh2lo;
    const __nv_bfloat16* wdyhi = (LAYER == 1) ? g_wdy1hi : g_wdy2hi;
    const __nv_bfloat16* wdylo = (LAYER == 1) ? g_wdy1lo : g_wdy2lo;
    float* dst = (LAYER == 1) ? (float*)g_y1 : dout;

    const int blk = blockIdx.x;
    const int b = blk >> 9, p = (blk >> 3) & 63, q = blk & 7;
    const int y0 = ((p >> 3) << 5) + (q << 2);
    const int x0 = (p & 7) << 5;
    const int bp = b * 64 + p;
    constexpr int NS = CIN / 16;
    constexpr int NC = 9 * NS;

    float d[4][4][4];
    #pragma unroll
    for (int i = 0; i < 4; ++i)
        #pragma unroll
        for (int j = 0; j < 4; ++j)
            #pragma unroll
            for (int k = 0; k < 4; ++k) d[i][j][k] = 0.f;

    // ldmatrix lane addresses (row stride 48B)
    const uint32_t laneA = (uint32_t)(lane & 15) * 48 + (uint32_t)(lane >> 4) * 16;
    const uint32_t laneW = (uint32_t)((lane & 7) + ((lane >> 4) << 3)) * 48 +
                           (uint32_t)((lane >> 3) & 1) * 16;

    const int px = tid >> 1, seg = tid & 1;    // A row / 16B seg
    const int wrow = tid >> 1;                 // W row

    uint4 pfA[2], pfW[2];

    auto prefetch = [&](int cc) {
        const int tap = cc / NS, sub = cc - tap * NS;
        const int ky = tap / 3, kx = tap - ky * 3;
        const int y = y0 + (px >> 5) + ky;
        const int x = x0 + (px & 31) + kx;
        const size_t aoff = (((size_t)b * PW + y) * PW + x) * CIN + sub * 16 + seg * 8;
        pfA[0] = *(const uint4*)(xhi + aoff);
        pfA[1] = *(const uint4*)(xlo + aoff);
        if (wrow < 64) {
            const size_t woff = (size_t)cc * 1024 + wrow * 16 + seg * 8;
            pfW[0] = *(const uint4*)(wshhi + woff);
            pfW[1] = *(const uint4*)(wshlo + woff);
        } else {
            const size_t woff = ((size_t)bp * NC + cc) * 1024 + (wrow - 64) * 16 + seg * 8;
            pfW[0] = *(const uint4*)(wdyhi + woff);
            pfW[1] = *(const uint4*)(wdylo + woff);
        }
    };
    auto sts = [&](int buf) {
        unsigned char* bb = sm + buf * S_BUF;
        *(uint4*)(bb + px * 48 + seg * 16)          = pfA[0];
        *(uint4*)(bb + S_ALO + px * 48 + seg * 16)  = pfA[1];
        *(uint4*)(bb + S_WHI + wrow * 48 + seg * 16) = pfW[0];
        *(uint4*)(bb + S_WLO + wrow * 48 + seg * 16) = pfW[1];
    };

    prefetch(0);
    sts(0);
    if (NC > 1) prefetch(1);
    __syncthreads();

    for (int cc = 0; cc < NC; ++cc) {
        const int buf = cc & 1;
        const uint32_t bufb = sbase + buf * S_BUF;
        const uint32_t Ah = bufb + wm * 3072 + laneA;
        const uint32_t Al = Ah + S_ALO;
        const uint32_t Wh = bufb + S_WHI + wn * 1536 + laneW;
        const uint32_t Wl = Wh + 6144;
        uint32_t a[4][4], al[4][4], w[2][4], v[2][4];

        // ---- front-load Ah, Wh, Wl fragments (latency absorbed before pass 1) ----
        #pragma unroll
        for (int mf = 0; mf < 4; ++mf) LDM4(a[mf], Ah + mf * 768);
        #pragma unroll
        for (int nf = 0; nf < 2; ++nf) LDM4(w[nf], Wh + nf * 768);
        #pragma unroll
        for (int nf = 0; nf < 2; ++nf) LDM4(v[nf], Wl + nf * 768);

        // ---- pass 1: Ah * Wh ----
        #pragma unroll
        for (int mf = 0; mf < 4; ++mf)
            #pragma unroll
            for (int nf = 0; nf < 2; ++nf) {
                MMA(d[mf][nf * 2],     a[mf], w[nf][0], w[nf][1]);
                MMA(d[mf][nf * 2 + 1], a[mf], w[nf][2], w[nf][3]);
            }

        // ---- hoist Al loads: latency hides under pass-2 MMAs ----
        #pragma unroll
        for (int mf = 0; mf < 4; ++mf) LDM4(al[mf], Al + mf * 768);

        // ---- pass 2: Ah * Wl ----
        #pragma unroll
        for (int mf = 0; mf < 4; ++mf)
            #pragma unroll
            for (int nf = 0; nf < 2; ++nf) {
                MMA(d[mf][nf * 2],     a[mf], v[nf][0], v[nf][1]);
                MMA(d[mf][nf * 2 + 1], a[mf], v[nf][2], v[nf][3]);
            }

        // ---- pass 3: Al * Wh (fragments already resident) ----
        #pragma unroll
        for (int mf = 0; mf < 4; ++mf)
            #pragma unroll
            for (int nf = 0; nf < 2; ++nf) {
                MMA(d[mf][nf * 2],     al[mf], w[nf][0], w[nf][1]);
                MMA(d[mf][nf * 2 + 1], al[mf], w[nf][2], w[nf][3]);
            }

        // ---- fill other buffer for next chunk, start LDG for chunk+2 ----
        if (cc + 1 < NC) {
            sts(buf ^ 1);
            if (cc + 2 < NC) prefetch(cc + 2);
            __syncthreads();
        }
    }

    // ---- epilogue: store + fused BN stats ----
    float* gsum = (LAYER == 1) ? g_sum1 : g_sum2;
    float* gsqs = (LAYER == 1) ? g_sqs1 : g_sqs2;
    const int r4 = lane >> 2;
    const int c2 = (lane & 3) << 1;
    #pragma unroll
    for (int mf = 0; mf < 4; ++mf) {
        int pxA = wm * 64 + mf * 16 + r4;
        int pxB = pxA + 8;
        size_t pixA = (size_t)(y0 + (pxA >> 5)) * 256 + x0 + (pxA & 31);
        size_t pixB = (size_t)(y0 + (pxB >> 5)) * 256 + x0 + (pxB & 31);
        #pragma unroll
        for (int n8 = 0; n8 < 4; ++n8) {
            int oc = wn * 32 + n8 * 8 + c2;
            size_t base = ((size_t)(b * 128 + oc)) << 16;
            dst[base + pixA]         = d[mf][n8][0];
            dst[base + 65536 + pixA] = d[mf][n8][1];
            dst[base + pixB]         = d[mf][n8][2];
            dst[base + 65536 + pixB] = d[mf][n8][3];
        }
    }
    #pragma unroll
    for (int n8 = 0; n8 < 4; ++n8) {
        float sA = 0.f, qA = 0.f, sB = 0.f, qB = 0.f;
        #pragma unroll
        for (int mf = 0; mf < 4; ++mf) {
            float e0 = d[mf][n8][0], e1 = d[mf][n8][1];
            float e2 = d[mf][n8][2], e3 = d[mf][n8][3];
            sA += e0 + e2; qA = fmaf(e0, e0, fmaf(e2, e2, qA));
            sB += e1 + e3; qB = fmaf(e1, e1, fmaf(e3, e3, qB));
        }
        #pragma unroll
        for (int off = 16; off >= 4; off >>= 1) {
            sA += __shfl_down_sync(0xffffffffu, sA, off);
            qA += __shfl_down_sync(0xffffffffu, qA, off);
            sB += __shfl_down_sync(0xffffffffu, sB, off);
            qB += __shfl_down_sync(0xffffffffu, qB, off);
        }
        if (lane < 4) {
            int oc = wn * 32 + n8 * 8 + c2;
            atomicAdd(&gsum[oc], sA);     atomicAdd(&gsqs[oc], qA);
            atomicAdd(&gsum[oc + 1], sB); atomicAdd(&gsqs[oc + 1], qB);
        }
    }
}

// ---------------- BN finalize / apply -------------------------------------------
__global__ void finalize_stats_kernel(const float* __restrict__ gamma,
                                      const float* __restrict__ beta, int layer)
{
    int c = threadIdx.x;
    if (c >= 128) return;
    const float invN = 1.f / (float)((size_t)BATCH * 256 * 256);
    float s = (layer == 1) ? g_sum1[c] : g_sum2[c];
    float q = (layer == 1) ? g_sqs1[c] : g_sqs2[c];
    float m = s * invN;
    float var = fmaf(-m, m, q * invN);
    float inv = rsqrtf(var + EPSBN);
    float a = gamma[c] * inv;
    float bb = fmaf(-a, m, beta[c]);
    if (layer == 1) { g_a1[c] = a; g_b1[c] = bb; }
    else            { g_a2[c] = a; g_b2[c] = bb; }
}

__global__ void apply_bn2_kernel(float4* __restrict__ out)
{
    const size_t n4 = (size_t)BATCH * 128 * 256 * 256 / 4;
    for (size_t i = (size_t)blockIdx.x * blockDim.x + threadIdx.x; i < n4;
         i += (size_t)gridDim.x * blockDim.x) {
        int c = (int)((i >> 14) & 127);
        float a = g_a2[c], bb = g_b2[c];
        float4 v = out[i];
        v.x = fmaxf(0.f, fmaf(a, v.x, bb));
        v.y = fmaxf(0.f, fmaf(a, v.y, bb));
        v.z = fmaxf(0.f, fmaf(a, v.z, bb));
        v.w = fmaxf(0.f, fmaf(a, v.w, bb));
        out[i] = v;
    }
}

// ---------------- launcher (harness pointers ONLY as kernel args) ----------------
extern "C" void kernel_launch(void* const* d_in, const int* in_sizes, int n_in,
                              void* d_out, int out_size)
{
    const float* x      = (const float*)d_in[0];
    const float* cw     = (const float*)d_in[1];
    const float* w1     = (const float*)d_in[2];
    const float* w2     = (const float*)d_in[3];
    const float* gamma1 = (const float*)d_in[4];
    const float* beta1  = (const float*)d_in[5];
    const float* gamma2 = (const float*)d_in[6];
    const float* beta2  = (const float*)d_in[7];
    float* out = (float*)d_out;

    zero_stats_kernel<<<1, 128>>>();
    zero_border_kernel<<<33, 256>>>();
    wprep_sh_kernel<64, 1><<<16, 256>>>(w1);
    wprep_sh_kernel<128, 2><<<32, 256>>>(w2);
    wprep_dy_kernel<64, 0, 1><<<8192, 256>>>(cw);
    wprep_dy_kernel<128, WOFF2, 2><<<16384, 256>>>(cw);

    // layer 1
    xsplit_kernel<64, 1><<<8192, 256>>>(x);
    conv_mma_kernel<64, 1><<<4096, 256>>>(nullptr);
    finalize_stats_kernel<<<1, 128>>>(gamma1, beta1, 1);

    // layer 2 (BN1+ReLU fused into xsplit)
    xsplit_kernel<128, 2><<<8192, 256>>>(nullptr);
    conv_mma_kernel<128, 2><<<4096, 256>>>(out);
    finalize_stats_kernel<<<1, 128>>>(gamma2, beta2, 2);

    apply_bn2_kernel<<<8192, 256>>>((float4*)out);
}